// round 3
// baseline (speedup 1.0000x reference)
#include <cuda_runtime.h>
#include <math.h>
#include <stdint.h>

// Problem constants
#define B_SZ 4
#define NSEQ 2048
#define DIM  1024
#define MX   (B_SZ * NSEQ)

// Scratch (device globals — no allocation allowed)
__device__ float g_q[(size_t)B_SZ * NSEQ * DIM];
__device__ float g_k[(size_t)B_SZ * NSEQ * DIM];
__device__ float g_v[(size_t)B_SZ * NSEQ * DIM];
__device__ float g_s[(size_t)B_SZ * NSEQ * NSEQ];

// ---------------------------------------------------------------------------
// TF32 tensor-core GEMM: C = scale * (A @ op(B)) [+ bias]
//   A: [M,K] row-major.
//   BT=true : B is [N,K] row-major (NT)
//   BT=false: B is [K,N] row-major (NN)
// Tiles: CTA 128x128, BK=16, 8 warps (2x4), warp tile 64x32,
// mma.sync m16n8k8 tf32. M,N % 128 == 0, K % 16 == 0 (all hold here).
// ---------------------------------------------------------------------------
#define BM 128
#define BN 128
#define BK 16
#define ASTR 20     // padded stride for [row][k] tiles: (g*20+t) mod 32 is a permutation
#define BSTR 136    // padded stride for [k][n] tile (NN): (t*136+g) mod 32 -> t*8+g, permutation

__device__ __forceinline__ uint32_t f2tf32(float f) {
    uint32_t u;
    asm("cvt.rna.tf32.f32 %0, %1;" : "=r"(u) : "f"(f));
    return u;
}

__device__ __forceinline__ void mma_tf32(float* c, const uint32_t* a, const uint32_t* b) {
    asm volatile(
        "mma.sync.aligned.m16n8k8.row.col.f32.tf32.tf32.f32 "
        "{%0,%1,%2,%3}, {%4,%5,%6,%7}, {%8,%9}, {%0,%1,%2,%3};"
        : "+f"(c[0]), "+f"(c[1]), "+f"(c[2]), "+f"(c[3])
        : "r"(a[0]), "r"(a[1]), "r"(a[2]), "r"(a[3]),
          "r"(b[0]), "r"(b[1]));
}

template <bool BT>
__global__ __launch_bounds__(256, 2)
void gemm_tf32(const float* __restrict__ A, const float* __restrict__ Bm,
               const float* __restrict__ bias, float* __restrict__ C,
               int M, int N, int K, float scale,
               long long sA, long long sB, long long sC)
{
    __shared__ uint32_t As[BM * ASTR];                 // [m][k], stride 20
    __shared__ uint32_t Bs[BM * ASTR];                 // NT: [n][k] stride 20; NN: [k][n] stride 136 (fits)

    const int tid = threadIdx.x;
    const int bz  = blockIdx.z;
    A  += (size_t)bz * sA;
    Bm += (size_t)bz * sB;
    C  += (size_t)bz * sC;

    const int bm0 = blockIdx.y * BM;
    const int bn0 = blockIdx.x * BN;

    // ---- gmem loaders (register-staged prefetch) ----
    // A tile (and NT B tile): 128 rows x 16 cols = 512 float4; 2 per thread.
    const int lr = tid >> 2;            // 0..63  (row), second half at +64
    const int lc = (tid & 3) << 2;      // 0,4,8,12 (k)
    // NN B tile: 16 rows(k) x 128 cols = 512 float4; 2 per thread.
    const int nk = tid >> 5;            // 0..7 (k row), second at +8
    const int nc = (tid & 31) << 2;     // n col (0..124)

    float4 ra[2], rb[2];

    auto loadA = [&](int kt) {
#pragma unroll
        for (int r = 0; r < 2; r++)
            ra[r] = *(const float4*)(A + (size_t)(bm0 + lr + r * 64) * K + kt + lc);
    };
    auto loadB = [&](int kt) {
        if (BT) {
#pragma unroll
            for (int r = 0; r < 2; r++)
                rb[r] = *(const float4*)(Bm + (size_t)(bn0 + lr + r * 64) * K + kt + lc);
        } else {
#pragma unroll
            for (int r = 0; r < 2; r++)
                rb[r] = *(const float4*)(Bm + (size_t)(nk + r * 8) * N + bn0 + nc);
        }
    };
    auto loadB_at = [&](int kt) {
        if (BT) loadB(kt);
        else {
#pragma unroll
            for (int r = 0; r < 2; r++)
                rb[r] = *(const float4*)(Bm + (size_t)(kt + nk + r * 8) * N + bn0 + nc);
        }
    };
    auto stsA = [&]() {
#pragma unroll
        for (int r = 0; r < 2; r++) {
            uint32_t* p = &As[(lr + r * 64) * ASTR + lc];
            p[0] = f2tf32(ra[r].x); p[1] = f2tf32(ra[r].y);
            p[2] = f2tf32(ra[r].z); p[3] = f2tf32(ra[r].w);
        }
    };
    auto stsB = [&]() {
        if (BT) {
#pragma unroll
            for (int r = 0; r < 2; r++) {
                uint32_t* p = &Bs[(lr + r * 64) * ASTR + lc];
                p[0] = f2tf32(rb[r].x); p[1] = f2tf32(rb[r].y);
                p[2] = f2tf32(rb[r].z); p[3] = f2tf32(rb[r].w);
            }
        } else {
#pragma unroll
            for (int r = 0; r < 2; r++) {
                uint32_t* p = &Bs[(nk + r * 8) * BSTR + nc];
                p[0] = f2tf32(rb[r].x); p[1] = f2tf32(rb[r].y);
                p[2] = f2tf32(rb[r].z); p[3] = f2tf32(rb[r].w);
            }
        }
    };

    // ---- warp/fragment mapping ----
    const int wid  = tid >> 5;
    const int lane = tid & 31;
    const int g = lane >> 2;            // 0..7
    const int t = lane & 3;             // 0..3
    const int wm = (wid >> 2) * 64;     // warp row origin: 0 / 64
    const int wn = (wid & 3) * 32;      // warp col origin: 0/32/64/96

    float acc[4][4][4];
#pragma unroll
    for (int mi = 0; mi < 4; mi++)
#pragma unroll
        for (int ni = 0; ni < 4; ni++)
#pragma unroll
            for (int r = 0; r < 4; r++) acc[mi][ni][r] = 0.0f;

    loadA(0);
    loadB_at(0);

    for (int kt = 0; kt < K; kt += BK) {
        stsA();
        stsB();
        __syncthreads();

        if (kt + BK < K) {
            loadA(kt + BK);
            loadB_at(kt + BK);
        }

#pragma unroll
        for (int ks = 0; ks < 2; ks++) {
            const int k0 = ks * 8;
            uint32_t af[4][4];
#pragma unroll
            for (int mi = 0; mi < 4; mi++) {
                const int r0 = wm + mi * 16 + g;
                af[mi][0] = As[r0 * ASTR + k0 + t];
                af[mi][1] = As[(r0 + 8) * ASTR + k0 + t];
                af[mi][2] = As[r0 * ASTR + k0 + t + 4];
                af[mi][3] = As[(r0 + 8) * ASTR + k0 + t + 4];
            }
            uint32_t bf[4][2];
#pragma unroll
            for (int ni = 0; ni < 4; ni++) {
                const int n0 = wn + ni * 8 + g;
                if (BT) {
                    bf[ni][0] = Bs[n0 * ASTR + k0 + t];
                    bf[ni][1] = Bs[n0 * ASTR + k0 + t + 4];
                } else {
                    bf[ni][0] = Bs[(k0 + t) * BSTR + n0];
                    bf[ni][1] = Bs[(k0 + t + 4) * BSTR + n0];
                }
            }
#pragma unroll
            for (int mi = 0; mi < 4; mi++)
#pragma unroll
                for (int ni = 0; ni < 4; ni++)
                    mma_tf32(acc[mi][ni], af[mi], bf[ni]);
        }
        __syncthreads();
    }

    // ---- epilogue: scale, bias, float2 stores ----
    float bfr[4][2];
#pragma unroll
    for (int ni = 0; ni < 4; ni++) {
        const int col = bn0 + wn + ni * 8 + t * 2;
        bfr[ni][0] = bias ? bias[col] : 0.0f;
        bfr[ni][1] = bias ? bias[col + 1] : 0.0f;
    }
#pragma unroll
    for (int mi = 0; mi < 4; mi++) {
        const int row0 = bm0 + wm + mi * 16 + g;
#pragma unroll
        for (int ni = 0; ni < 4; ni++) {
            const int col = bn0 + wn + ni * 8 + t * 2;
            float2 v0, v1;
            v0.x = acc[mi][ni][0] * scale + bfr[ni][0];
            v0.y = acc[mi][ni][1] * scale + bfr[ni][1];
            v1.x = acc[mi][ni][2] * scale + bfr[ni][0];
            v1.y = acc[mi][ni][3] * scale + bfr[ni][1];
            *(float2*)(C + (size_t)row0 * N + col)       = v0;
            *(float2*)(C + (size_t)(row0 + 8) * N + col) = v1;
        }
    }
}

// ---------------------------------------------------------------------------
// Row softmax over N=2048 elements, one block per row, in place.
// ---------------------------------------------------------------------------
__global__ __launch_bounds__(256)
void softmax_kernel(float* __restrict__ S)
{
    const int n = NSEQ;
    float* row = S + (size_t)blockIdx.x * n;
    const int tid  = threadIdx.x;
    const int lane = tid & 31;
    const int wid  = tid >> 5;
    __shared__ float red[8];

    float m = -INFINITY;
    for (int i = tid; i < n; i += 256) m = fmaxf(m, row[i]);
#pragma unroll
    for (int o = 16; o > 0; o >>= 1) m = fmaxf(m, __shfl_xor_sync(0xffffffffu, m, o));
    if (lane == 0) red[wid] = m;
    __syncthreads();
    m = red[0];
#pragma unroll
    for (int i = 1; i < 8; i++) m = fmaxf(m, red[i]);
    __syncthreads();

    float s = 0.0f;
    for (int i = tid; i < n; i += 256) {
        float e = __expf(row[i] - m);
        row[i] = e;
        s += e;
    }
#pragma unroll
    for (int o = 16; o > 0; o >>= 1) s += __shfl_xor_sync(0xffffffffu, s, o);
    if (lane == 0) red[wid] = s;
    __syncthreads();
    float tot = red[0];
#pragma unroll
    for (int i = 1; i < 8; i++) tot += red[i];
    const float inv = 1.0f / tot;

    for (int i = tid; i < n; i += 256) row[i] *= inv;
}

// ---------------------------------------------------------------------------
// Launch
// ---------------------------------------------------------------------------
extern "C" void kernel_launch(void* const* d_in, const int* in_sizes, int n_in,
                              void* d_out, int out_size)
{
    const float* x  = (const float*)d_in[0];
    const float* Wq = (const float*)d_in[1];
    const float* bq = (const float*)d_in[2];
    const float* Wk = (const float*)d_in[3];
    const float* bk = (const float*)d_in[4];
    const float* Wv = (const float*)d_in[5];
    const float* bv = (const float*)d_in[6];
    float* out = (float*)d_out;

    float *q, *k, *v, *s;
    cudaGetSymbolAddress((void**)&q, g_q);
    cudaGetSymbolAddress((void**)&k, g_k);
    cudaGetSymbolAddress((void**)&v, g_v);
    cudaGetSymbolAddress((void**)&s, g_s);

    const float attn_scale = 1.0f / sqrtf((float)DIM);   // 1/32

    dim3 block(256);

    // 1) QKV projections: [8192,1024] = x @ W^T + b   (NT)
    {
        dim3 grid(DIM / BN, MX / BM, 1);
        gemm_tf32<true><<<grid, block>>>(x, Wq, bq, q, MX, DIM, DIM, 1.0f, 0, 0, 0);
        gemm_tf32<true><<<grid, block>>>(x, Wk, bk, k, MX, DIM, DIM, 1.0f, 0, 0, 0);
        gemm_tf32<true><<<grid, block>>>(x, Wv, bv, v, MX, DIM, DIM, 1.0f, 0, 0, 0);
    }

    // 2) S = scale * Q @ K^T   (per-batch, NT)
    {
        dim3 grid(NSEQ / BN, NSEQ / BM, B_SZ);
        gemm_tf32<true><<<grid, block>>>(q, k, nullptr, s,
                                         NSEQ, NSEQ, DIM, attn_scale,
                                         (long long)NSEQ * DIM,
                                         (long long)NSEQ * DIM,
                                         (long long)NSEQ * NSEQ);
    }

    // 3) softmax rows
    softmax_kernel<<<B_SZ * NSEQ, 256>>>(s);

    // 4) out = P @ V   (per-batch, NN)
    {
        dim3 grid(DIM / BN, NSEQ / BM, B_SZ);
        gemm_tf32<false><<<grid, block>>>(s, v, nullptr, out,
                                          NSEQ, DIM, NSEQ, 1.0f,
                                          (long long)NSEQ * NSEQ,
                                          (long long)NSEQ * DIM,
                                          (long long)NSEQ * DIM);
    }
}

// round 4
// speedup vs baseline: 1.0014x; 1.0014x over previous
#include <cuda_runtime.h>
#include <math.h>
#include <stdint.h>

// Problem constants
#define B_SZ 4
#define NSEQ 2048
#define DIM  1024
#define MX   (B_SZ * NSEQ)

// Scratch (device globals — no allocation allowed)
__device__ float g_q[(size_t)B_SZ * NSEQ * DIM];
__device__ float g_k[(size_t)B_SZ * NSEQ * DIM];
__device__ float g_v[(size_t)B_SZ * NSEQ * DIM];
__device__ float g_s[(size_t)B_SZ * NSEQ * NSEQ];

// ---------------------------------------------------------------------------
// TF32 tensor-core GEMM: C = scale * (A @ op(B)) [+ bias]
//   A: [M,K] row-major.
//   BT=true : B is [N,K] row-major (NT)
//   BT=false: B is [K,N] row-major (NN)
// Tiles: CTA 128x128, BK=16, 8 warps (2x4), warp tile 64x32,
// mma.sync m16n8k8 tf32. M,N % 128 == 0, K % 16 == 0 (all hold here).
// ---------------------------------------------------------------------------
#define BM 128
#define BN 128
#define BK 16
#define ASTR 20     // padded stride for [row][k] tiles: (g*20+t) mod 32 is a permutation
#define BSTR 136    // padded stride for [k][n] tile (NN): (t*136+g) mod 32 -> t*8+g, permutation

__device__ __forceinline__ uint32_t f2tf32(float f) {
    uint32_t u;
    asm("cvt.rna.tf32.f32 %0, %1;" : "=r"(u) : "f"(f));
    return u;
}

__device__ __forceinline__ void mma_tf32(float* c, const uint32_t* a, const uint32_t* b) {
    asm volatile(
        "mma.sync.aligned.m16n8k8.row.col.f32.tf32.tf32.f32 "
        "{%0,%1,%2,%3}, {%4,%5,%6,%7}, {%8,%9}, {%0,%1,%2,%3};"
        : "+f"(c[0]), "+f"(c[1]), "+f"(c[2]), "+f"(c[3])
        : "r"(a[0]), "r"(a[1]), "r"(a[2]), "r"(a[3]),
          "r"(b[0]), "r"(b[1]));
}

template <bool BT>
__global__ __launch_bounds__(256, 2)
void gemm_tf32(const float* __restrict__ A, const float* __restrict__ Bm,
               const float* __restrict__ bias, float* __restrict__ C,
               int M, int N, int K, float scale,
               long long sA, long long sB, long long sC)
{
    __shared__ uint32_t As[BM * ASTR];                 // [m][k], stride 20
    __shared__ uint32_t Bs[BM * ASTR];                 // NT: [n][k] stride 20; NN: [k][n] stride 136 (fits)

    const int tid = threadIdx.x;
    const int bz  = blockIdx.z;
    A  += (size_t)bz * sA;
    Bm += (size_t)bz * sB;
    C  += (size_t)bz * sC;

    const int bm0 = blockIdx.y * BM;
    const int bn0 = blockIdx.x * BN;

    // ---- gmem loaders (register-staged prefetch) ----
    // A tile (and NT B tile): 128 rows x 16 cols = 512 float4; 2 per thread.
    const int lr = tid >> 2;            // 0..63  (row), second half at +64
    const int lc = (tid & 3) << 2;      // 0,4,8,12 (k)
    // NN B tile: 16 rows(k) x 128 cols = 512 float4; 2 per thread.
    const int nk = tid >> 5;            // 0..7 (k row), second at +8
    const int nc = (tid & 31) << 2;     // n col (0..124)

    float4 ra[2], rb[2];

    auto loadA = [&](int kt) {
#pragma unroll
        for (int r = 0; r < 2; r++)
            ra[r] = *(const float4*)(A + (size_t)(bm0 + lr + r * 64) * K + kt + lc);
    };
    auto loadB = [&](int kt) {
        if (BT) {
#pragma unroll
            for (int r = 0; r < 2; r++)
                rb[r] = *(const float4*)(Bm + (size_t)(bn0 + lr + r * 64) * K + kt + lc);
        } else {
#pragma unroll
            for (int r = 0; r < 2; r++)
                rb[r] = *(const float4*)(Bm + (size_t)(nk + r * 8) * N + bn0 + nc);
        }
    };
    auto loadB_at = [&](int kt) {
        if (BT) loadB(kt);
        else {
#pragma unroll
            for (int r = 0; r < 2; r++)
                rb[r] = *(const float4*)(Bm + (size_t)(kt + nk + r * 8) * N + bn0 + nc);
        }
    };
    auto stsA = [&]() {
#pragma unroll
        for (int r = 0; r < 2; r++) {
            uint32_t* p = &As[(lr + r * 64) * ASTR + lc];
            p[0] = f2tf32(ra[r].x); p[1] = f2tf32(ra[r].y);
            p[2] = f2tf32(ra[r].z); p[3] = f2tf32(ra[r].w);
        }
    };
    auto stsB = [&]() {
        if (BT) {
#pragma unroll
            for (int r = 0; r < 2; r++) {
                uint32_t* p = &Bs[(lr + r * 64) * ASTR + lc];
                p[0] = f2tf32(rb[r].x); p[1] = f2tf32(rb[r].y);
                p[2] = f2tf32(rb[r].z); p[3] = f2tf32(rb[r].w);
            }
        } else {
#pragma unroll
            for (int r = 0; r < 2; r++) {
                uint32_t* p = &Bs[(nk + r * 8) * BSTR + nc];
                p[0] = f2tf32(rb[r].x); p[1] = f2tf32(rb[r].y);
                p[2] = f2tf32(rb[r].z); p[3] = f2tf32(rb[r].w);
            }
        }
    };

    // ---- warp/fragment mapping ----
    const int wid  = tid >> 5;
    const int lane = tid & 31;
    const int g = lane >> 2;            // 0..7
    const int t = lane & 3;             // 0..3
    const int wm = (wid >> 2) * 64;     // warp row origin: 0 / 64
    const int wn = (wid & 3) * 32;      // warp col origin: 0/32/64/96

    float acc[4][4][4];
#pragma unroll
    for (int mi = 0; mi < 4; mi++)
#pragma unroll
        for (int ni = 0; ni < 4; ni++)
#pragma unroll
            for (int r = 0; r < 4; r++) acc[mi][ni][r] = 0.0f;

    loadA(0);
    loadB_at(0);

    for (int kt = 0; kt < K; kt += BK) {
        stsA();
        stsB();
        __syncthreads();

        if (kt + BK < K) {
            loadA(kt + BK);
            loadB_at(kt + BK);
        }

#pragma unroll
        for (int ks = 0; ks < 2; ks++) {
            const int k0 = ks * 8;
            uint32_t af[4][4];
#pragma unroll
            for (int mi = 0; mi < 4; mi++) {
                const int r0 = wm + mi * 16 + g;
                af[mi][0] = As[r0 * ASTR + k0 + t];
                af[mi][1] = As[(r0 + 8) * ASTR + k0 + t];
                af[mi][2] = As[r0 * ASTR + k0 + t + 4];
                af[mi][3] = As[(r0 + 8) * ASTR + k0 + t + 4];
            }
            uint32_t bf[4][2];
#pragma unroll
            for (int ni = 0; ni < 4; ni++) {
                const int n0 = wn + ni * 8 + g;
                if (BT) {
                    bf[ni][0] = Bs[n0 * ASTR + k0 + t];
                    bf[ni][1] = Bs[n0 * ASTR + k0 + t + 4];
                } else {
                    bf[ni][0] = Bs[(k0 + t) * BSTR + n0];
                    bf[ni][1] = Bs[(k0 + t + 4) * BSTR + n0];
                }
            }
#pragma unroll
            for (int mi = 0; mi < 4; mi++)
#pragma unroll
                for (int ni = 0; ni < 4; ni++)
                    mma_tf32(acc[mi][ni], af[mi], bf[ni]);
        }
        __syncthreads();
    }

    // ---- epilogue: scale, bias, float2 stores ----
    float bfr[4][2];
#pragma unroll
    for (int ni = 0; ni < 4; ni++) {
        const int col = bn0 + wn + ni * 8 + t * 2;
        bfr[ni][0] = bias ? bias[col] : 0.0f;
        bfr[ni][1] = bias ? bias[col + 1] : 0.0f;
    }
#pragma unroll
    for (int mi = 0; mi < 4; mi++) {
        const int row0 = bm0 + wm + mi * 16 + g;
#pragma unroll
        for (int ni = 0; ni < 4; ni++) {
            const int col = bn0 + wn + ni * 8 + t * 2;
            float2 v0, v1;
            v0.x = acc[mi][ni][0] * scale + bfr[ni][0];
            v0.y = acc[mi][ni][1] * scale + bfr[ni][1];
            v1.x = acc[mi][ni][2] * scale + bfr[ni][0];
            v1.y = acc[mi][ni][3] * scale + bfr[ni][1];
            *(float2*)(C + (size_t)row0 * N + col)       = v0;
            *(float2*)(C + (size_t)(row0 + 8) * N + col) = v1;
        }
    }
}

// ---------------------------------------------------------------------------
// Row softmax over N=2048 elements, one block per row, in place.
// ---------------------------------------------------------------------------
__global__ __launch_bounds__(256)
void softmax_kernel(float* __restrict__ S)
{
    const int n = NSEQ;
    float* row = S + (size_t)blockIdx.x * n;
    const int tid  = threadIdx.x;
    const int lane = tid & 31;
    const int wid  = tid >> 5;
    __shared__ float red[8];

    float m = -INFINITY;
    for (int i = tid; i < n; i += 256) m = fmaxf(m, row[i]);
#pragma unroll
    for (int o = 16; o > 0; o >>= 1) m = fmaxf(m, __shfl_xor_sync(0xffffffffu, m, o));
    if (lane == 0) red[wid] = m;
    __syncthreads();
    m = red[0];
#pragma unroll
    for (int i = 1; i < 8; i++) m = fmaxf(m, red[i]);
    __syncthreads();

    float s = 0.0f;
    for (int i = tid; i < n; i += 256) {
        float e = __expf(row[i] - m);
        row[i] = e;
        s += e;
    }
#pragma unroll
    for (int o = 16; o > 0; o >>= 1) s += __shfl_xor_sync(0xffffffffu, s, o);
    if (lane == 0) red[wid] = s;
    __syncthreads();
    float tot = red[0];
#pragma unroll
    for (int i = 1; i < 8; i++) tot += red[i];
    const float inv = 1.0f / tot;

    for (int i = tid; i < n; i += 256) row[i] *= inv;
}

// ---------------------------------------------------------------------------
// Launch
// ---------------------------------------------------------------------------
extern "C" void kernel_launch(void* const* d_in, const int* in_sizes, int n_in,
                              void* d_out, int out_size)
{
    const float* x  = (const float*)d_in[0];
    const float* Wq = (const float*)d_in[1];
    const float* bq = (const float*)d_in[2];
    const float* Wk = (const float*)d_in[3];
    const float* bk = (const float*)d_in[4];
    const float* Wv = (const float*)d_in[5];
    const float* bv = (const float*)d_in[6];
    float* out = (float*)d_out;

    float *q, *k, *v, *s;
    cudaGetSymbolAddress((void**)&q, g_q);
    cudaGetSymbolAddress((void**)&k, g_k);
    cudaGetSymbolAddress((void**)&v, g_v);
    cudaGetSymbolAddress((void**)&s, g_s);

    const float attn_scale = 1.0f / sqrtf((float)DIM);   // 1/32

    dim3 block(256);

    // 1) QKV projections: [8192,1024] = x @ W^T + b   (NT)
    {
        dim3 grid(DIM / BN, MX / BM, 1);
        gemm_tf32<true><<<grid, block>>>(x, Wq, bq, q, MX, DIM, DIM, 1.0f, 0, 0, 0);
        gemm_tf32<true><<<grid, block>>>(x, Wk, bk, k, MX, DIM, DIM, 1.0f, 0, 0, 0);
        gemm_tf32<true><<<grid, block>>>(x, Wv, bv, v, MX, DIM, DIM, 1.0f, 0, 0, 0);
    }

    // 2) S = scale * Q @ K^T   (per-batch, NT)
    {
        dim3 grid(NSEQ / BN, NSEQ / BM, B_SZ);
        gemm_tf32<true><<<grid, block>>>(q, k, nullptr, s,
                                         NSEQ, NSEQ, DIM, attn_scale,
                                         (long long)NSEQ * DIM,
                                         (long long)NSEQ * DIM,
                                         (long long)NSEQ * NSEQ);
    }

    // 3) softmax rows
    softmax_kernel<<<B_SZ * NSEQ, 256>>>(s);

    // 4) out = P @ V   (per-batch, NN)
    {
        dim3 grid(DIM / BN, NSEQ / BM, B_SZ);
        gemm_tf32<false><<<grid, block>>>(s, v, nullptr, out,
                                          NSEQ, DIM, NSEQ, 1.0f,
                                          (long long)NSEQ * NSEQ,
                                          (long long)NSEQ * DIM,
                                          (long long)NSEQ * DIM);
    }
}

// round 5
// speedup vs baseline: 1.2384x; 1.2367x over previous
#include <cuda_runtime.h>
#include <math.h>
#include <stdint.h>

// Problem constants
#define B_SZ 4
#define NSEQ 2048
#define DIM  1024
#define MX   (B_SZ * NSEQ)

// Scratch (device globals — no allocation allowed)
__device__ float g_q [(size_t)B_SZ * NSEQ * DIM];
__device__ float g_k [(size_t)B_SZ * NSEQ * DIM];
__device__ float g_vt[(size_t)B_SZ * DIM * NSEQ];   // V transposed: [b][d][m]
__device__ float g_s [(size_t)B_SZ * NSEQ * NSEQ];

// ---------------------------------------------------------------------------
// TF32 tensor-core NT GEMM: C = scale * (A @ B^T) [+ bias]
//   A: [M,K] row-major, B: [N,K] row-major.
//   TSTORE=true: store C transposed per batch-of-2048 rows:
//       Ct[(row/2048)*N + col][row%2048]  (used to produce V^T)
// CTA 128x128, BK=16, 8 warps (2x4), warp tile 64x32, mma m16n8k8 tf32,
// double-buffered smem, ldmatrix fragment loads.
// Requires M,N % 128 == 0, K % 16 == 0.
// ---------------------------------------------------------------------------
#define BM 128
#define BN 128
#define BK 16
#define ASTR 20   // padded k-stride (words); conflict-free for ldmatrix + mostly for STS

__device__ __forceinline__ uint32_t f2tf32(float f) {
    uint32_t u;
    asm("cvt.rna.tf32.f32 %0, %1;" : "=r"(u) : "f"(f));
    return u;
}

__device__ __forceinline__ void mma_tf32(float* c, const uint32_t* a, const uint32_t* b) {
    asm volatile(
        "mma.sync.aligned.m16n8k8.row.col.f32.tf32.tf32.f32 "
        "{%0,%1,%2,%3}, {%4,%5,%6,%7}, {%8,%9}, {%0,%1,%2,%3};"
        : "+f"(c[0]), "+f"(c[1]), "+f"(c[2]), "+f"(c[3])
        : "r"(a[0]), "r"(a[1]), "r"(a[2]), "r"(a[3]),
          "r"(b[0]), "r"(b[1]));
}

__device__ __forceinline__ void ldsm4(uint32_t* r, uint32_t saddr) {
    asm volatile("ldmatrix.sync.aligned.m8n8.x4.shared.b16 {%0,%1,%2,%3}, [%4];"
                 : "=r"(r[0]), "=r"(r[1]), "=r"(r[2]), "=r"(r[3])
                 : "r"(saddr));
}

template <bool TSTORE>
__global__ __launch_bounds__(256, 2)
void gemm_nt(const float* __restrict__ A, const float* __restrict__ Bm,
             const float* __restrict__ bias, float* __restrict__ C,
             int M, int N, int K, float scale,
             long long sA, long long sB, long long sC)
{
    __shared__ uint32_t As[2][BM * ASTR];
    __shared__ uint32_t Bs[2][BM * ASTR];

    const int tid = threadIdx.x;
    const int bz  = blockIdx.z;
    A  += (size_t)bz * sA;
    Bm += (size_t)bz * sB;
    C  += (size_t)bz * sC;

    const int bm0 = blockIdx.y * BM;
    const int bn0 = blockIdx.x * BN;

    // ---- gmem loaders: 128 rows x 16 k = 512 float4; 2 per thread ----
    const int lr = tid >> 2;            // 0..63 (+64 for second)
    const int lc = (tid & 3) << 2;      // 0,4,8,12
    const float* aptr = A  + (size_t)(bm0 + lr) * K + lc;
    const float* bptr = Bm + (size_t)(bn0 + lr) * K + lc;
    const size_t rstep = (size_t)64 * K;

    float4 ra[2], rb[2];

    // ---- warp/fragment mapping ----
    const int wid  = tid >> 5;
    const int lane = tid & 31;
    const int g = lane >> 2;
    const int t = lane & 3;
    const int wm = (wid >> 2) * 64;     // 0 / 64
    const int wn = (wid & 3) * 32;      // 0/32/64/96

    // ldmatrix per-lane address components
    const int bsel = lane >> 3;         // block 0..3
    const int rr   = lane & 7;
    const int a_row = ((bsel & 1) << 3) + rr;   // +0/+8 row within 16
    const int a_kc  = (bsel >> 1) << 2;         // +0/+4 k
    const int b_row = ((bsel >> 1) << 3) + rr;  // +0/+8 row within 16
    const int b_kc  = (bsel & 1) << 2;          // +0/+4 k

    const uint32_t as_base = (uint32_t)__cvta_generic_to_shared(&As[0][0]);
    const uint32_t bs_base = (uint32_t)__cvta_generic_to_shared(&Bs[0][0]);
    // lane-resolved fragment base addresses (buf 0, mi/pr = 0, ks = 0)
    const uint32_t a_lane = as_base + (((wm + a_row) * ASTR + a_kc) << 2);
    const uint32_t b_lane = bs_base + (((wn + b_row) * ASTR + b_kc) << 2);
    const uint32_t bufstep = BM * ASTR * 4;

    float acc[4][4][4];
#pragma unroll
    for (int mi = 0; mi < 4; mi++)
#pragma unroll
        for (int ni = 0; ni < 4; ni++)
#pragma unroll
            for (int r = 0; r < 4; r++) acc[mi][ni][r] = 0.0f;

    // ---- prologue: load + store tile 0 ----
    ra[0] = *(const float4*)(aptr);
    ra[1] = *(const float4*)(aptr + rstep);
    rb[0] = *(const float4*)(bptr);
    rb[1] = *(const float4*)(bptr + rstep);
    aptr += BK; bptr += BK;
    {
        uint32_t* pa0 = &As[0][lr * ASTR + lc];
        uint32_t* pa1 = &As[0][(lr + 64) * ASTR + lc];
        pa0[0]=f2tf32(ra[0].x); pa0[1]=f2tf32(ra[0].y); pa0[2]=f2tf32(ra[0].z); pa0[3]=f2tf32(ra[0].w);
        pa1[0]=f2tf32(ra[1].x); pa1[1]=f2tf32(ra[1].y); pa1[2]=f2tf32(ra[1].z); pa1[3]=f2tf32(ra[1].w);
        uint32_t* pb0 = &Bs[0][lr * ASTR + lc];
        uint32_t* pb1 = &Bs[0][(lr + 64) * ASTR + lc];
        pb0[0]=f2tf32(rb[0].x); pb0[1]=f2tf32(rb[0].y); pb0[2]=f2tf32(rb[0].z); pb0[3]=f2tf32(rb[0].w);
        pb1[0]=f2tf32(rb[1].x); pb1[1]=f2tf32(rb[1].y); pb1[2]=f2tf32(rb[1].z); pb1[3]=f2tf32(rb[1].w);
    }
    __syncthreads();

    int buf = 0;
    for (int kt = 0; kt < K; kt += BK) {
        const bool more = (kt + BK < K);
        if (more) {
            ra[0] = *(const float4*)(aptr);
            ra[1] = *(const float4*)(aptr + rstep);
            rb[0] = *(const float4*)(bptr);
            rb[1] = *(const float4*)(bptr + rstep);
            aptr += BK; bptr += BK;
        }

        // ---- compute current buffer ----
        const uint32_t abase = a_lane + buf * bufstep;
        const uint32_t bbase = b_lane + buf * bufstep;
#pragma unroll
        for (int ks = 0; ks < 2; ks++) {
            const uint32_t ko = ks * 32;        // 8 words * 4B
            uint32_t af[4][4];
#pragma unroll
            for (int mi = 0; mi < 4; mi++)
                ldsm4(af[mi], abase + mi * (16 * ASTR * 4) + ko);
            uint32_t bf[2][4];
#pragma unroll
            for (int pr = 0; pr < 2; pr++)
                ldsm4(bf[pr], bbase + pr * (16 * ASTR * 4) + ko);
#pragma unroll
            for (int mi = 0; mi < 4; mi++)
#pragma unroll
                for (int ni = 0; ni < 4; ni++)
                    mma_tf32(acc[mi][ni], af[mi], &bf[ni >> 1][(ni & 1) * 2]);
        }

        // ---- stage next tile into the other buffer ----
        if (more) {
            const int nb = buf ^ 1;
            uint32_t* pa0 = &As[nb][lr * ASTR + lc];
            uint32_t* pa1 = &As[nb][(lr + 64) * ASTR + lc];
            pa0[0]=f2tf32(ra[0].x); pa0[1]=f2tf32(ra[0].y); pa0[2]=f2tf32(ra[0].z); pa0[3]=f2tf32(ra[0].w);
            pa1[0]=f2tf32(ra[1].x); pa1[1]=f2tf32(ra[1].y); pa1[2]=f2tf32(ra[1].z); pa1[3]=f2tf32(ra[1].w);
            uint32_t* pb0 = &Bs[nb][lr * ASTR + lc];
            uint32_t* pb1 = &Bs[nb][(lr + 64) * ASTR + lc];
            pb0[0]=f2tf32(rb[0].x); pb0[1]=f2tf32(rb[0].y); pb0[2]=f2tf32(rb[0].z); pb0[3]=f2tf32(rb[0].w);
            pb1[0]=f2tf32(rb[1].x); pb1[1]=f2tf32(rb[1].y); pb1[2]=f2tf32(rb[1].z); pb1[3]=f2tf32(rb[1].w);
            __syncthreads();
            buf = nb;
        }
    }

    // ---- epilogue ----
    float bfr[4][2];
#pragma unroll
    for (int ni = 0; ni < 4; ni++) {
        const int col = bn0 + wn + ni * 8 + t * 2;
        bfr[ni][0] = bias ? bias[col] : 0.0f;
        bfr[ni][1] = bias ? bias[col + 1] : 0.0f;
    }

    if (TSTORE) {
        // Ct[(row/2048)*N + col][row%2048]
#pragma unroll
        for (int mi = 0; mi < 4; mi++) {
            const int row0 = bm0 + wm + mi * 16 + g;
            const int bb = row0 >> 11;
            const int m0 = row0 & 2047;
#pragma unroll
            for (int ni = 0; ni < 4; ni++) {
                const int col = bn0 + wn + ni * 8 + t * 2;
                float* c0 = C + ((size_t)bb * N + col) * NSEQ;
                float* c1 = C + ((size_t)bb * N + col + 1) * NSEQ;
                c0[m0]     = acc[mi][ni][0] * scale + bfr[ni][0];
                c1[m0]     = acc[mi][ni][1] * scale + bfr[ni][1];
                c0[m0 + 8] = acc[mi][ni][2] * scale + bfr[ni][0];
                c1[m0 + 8] = acc[mi][ni][3] * scale + bfr[ni][1];
            }
        }
    } else {
#pragma unroll
        for (int mi = 0; mi < 4; mi++) {
            const int row0 = bm0 + wm + mi * 16 + g;
#pragma unroll
            for (int ni = 0; ni < 4; ni++) {
                const int col = bn0 + wn + ni * 8 + t * 2;
                float2 v0, v1;
                v0.x = acc[mi][ni][0] * scale + bfr[ni][0];
                v0.y = acc[mi][ni][1] * scale + bfr[ni][1];
                v1.x = acc[mi][ni][2] * scale + bfr[ni][0];
                v1.y = acc[mi][ni][3] * scale + bfr[ni][1];
                *(float2*)(C + (size_t)row0 * N + col)       = v0;
                *(float2*)(C + (size_t)(row0 + 8) * N + col) = v1;
            }
        }
    }
}

// ---------------------------------------------------------------------------
// Register-resident row softmax: N=2048, one block of 256 per row, in place.
// One gmem read + one gmem write per element.
// ---------------------------------------------------------------------------
__global__ __launch_bounds__(256)
void softmax_kernel(float* __restrict__ S)
{
    float4* row = (float4*)(S + (size_t)blockIdx.x * NSEQ);
    const int tid  = threadIdx.x;
    const int lane = tid & 31;
    const int wid  = tid >> 5;
    __shared__ float red[8];

    float4 v0 = row[tid];
    float4 v1 = row[tid + 256];

    float m = fmaxf(fmaxf(fmaxf(v0.x, v0.y), fmaxf(v0.z, v0.w)),
                    fmaxf(fmaxf(v1.x, v1.y), fmaxf(v1.z, v1.w)));
#pragma unroll
    for (int o = 16; o > 0; o >>= 1) m = fmaxf(m, __shfl_xor_sync(0xffffffffu, m, o));
    if (lane == 0) red[wid] = m;
    __syncthreads();
    m = red[0];
#pragma unroll
    for (int i = 1; i < 8; i++) m = fmaxf(m, red[i]);

    v0.x = __expf(v0.x - m); v0.y = __expf(v0.y - m);
    v0.z = __expf(v0.z - m); v0.w = __expf(v0.w - m);
    v1.x = __expf(v1.x - m); v1.y = __expf(v1.y - m);
    v1.z = __expf(v1.z - m); v1.w = __expf(v1.w - m);

    float s = v0.x + v0.y + v0.z + v0.w + v1.x + v1.y + v1.z + v1.w;
#pragma unroll
    for (int o = 16; o > 0; o >>= 1) s += __shfl_xor_sync(0xffffffffu, s, o);
    __syncthreads();               // red reuse safety
    if (lane == 0) red[wid] = s;
    __syncthreads();
    float tot = red[0];
#pragma unroll
    for (int i = 1; i < 8; i++) tot += red[i];
    const float inv = 1.0f / tot;

    v0.x *= inv; v0.y *= inv; v0.z *= inv; v0.w *= inv;
    v1.x *= inv; v1.y *= inv; v1.z *= inv; v1.w *= inv;
    row[tid]       = v0;
    row[tid + 256] = v1;
}

// ---------------------------------------------------------------------------
// Launch
// ---------------------------------------------------------------------------
extern "C" void kernel_launch(void* const* d_in, const int* in_sizes, int n_in,
                              void* d_out, int out_size)
{
    const float* x  = (const float*)d_in[0];
    const float* Wq = (const float*)d_in[1];
    const float* bq = (const float*)d_in[2];
    const float* Wk = (const float*)d_in[3];
    const float* bk = (const float*)d_in[4];
    const float* Wv = (const float*)d_in[5];
    const float* bv = (const float*)d_in[6];
    float* out = (float*)d_out;

    float *q, *k, *vt, *s;
    cudaGetSymbolAddress((void**)&q,  g_q);
    cudaGetSymbolAddress((void**)&k,  g_k);
    cudaGetSymbolAddress((void**)&vt, g_vt);
    cudaGetSymbolAddress((void**)&s,  g_s);

    const float attn_scale = 1.0f / sqrtf((float)DIM);   // 1/32

    dim3 block(256);

    // 1) QKV projections (NT). V writes its output transposed per batch.
    {
        dim3 grid(DIM / BN, MX / BM, 1);
        gemm_nt<false><<<grid, block>>>(x, Wq, bq, q,  MX, DIM, DIM, 1.0f, 0, 0, 0);
        gemm_nt<false><<<grid, block>>>(x, Wk, bk, k,  MX, DIM, DIM, 1.0f, 0, 0, 0);
        gemm_nt<true ><<<grid, block>>>(x, Wv, bv, vt, MX, DIM, DIM, 1.0f, 0, 0, 0);
    }

    // 2) S = scale * Q @ K^T   (per-batch NT)
    {
        dim3 grid(NSEQ / BN, NSEQ / BM, B_SZ);
        gemm_nt<false><<<grid, block>>>(q, k, nullptr, s,
                                        NSEQ, NSEQ, DIM, attn_scale,
                                        (long long)NSEQ * DIM,
                                        (long long)NSEQ * DIM,
                                        (long long)NSEQ * NSEQ);
    }

    // 3) softmax rows
    softmax_kernel<<<B_SZ * NSEQ, 256>>>(s);

    // 4) out = P @ Vt^T  (per-batch NT: out[n][d] = sum_m P[n][m] * Vt[d][m])
    {
        dim3 grid(DIM / BN, NSEQ / BM, B_SZ);
        gemm_nt<false><<<grid, block>>>(s, vt, nullptr, out,
                                        NSEQ, DIM, NSEQ, 1.0f,
                                        (long long)NSEQ * NSEQ,
                                        (long long)DIM * NSEQ,
                                        (long long)NSEQ * DIM);
    }
}

// round 6
// speedup vs baseline: 1.2386x; 1.0001x over previous
#include <cuda_runtime.h>
#include <math.h>
#include <stdint.h>

// Problem constants
#define B_SZ 4
#define NSEQ 2048
#define DIM  1024
#define MX   (B_SZ * NSEQ)

// Scratch (device globals — no allocation allowed)
__device__ float g_q [(size_t)B_SZ * NSEQ * DIM];
__device__ float g_k [(size_t)B_SZ * NSEQ * DIM];
__device__ float g_vt[(size_t)B_SZ * DIM * NSEQ];   // V transposed: [b][d][m]
__device__ float g_s [(size_t)B_SZ * NSEQ * NSEQ];

// ---------------------------------------------------------------------------
// TF32 tensor-core NT GEMM: C = scale * (A @ B^T) [+ bias]
//   A: [M,K] row-major, B: [N,K] row-major.
//   TSTORE=true: store C transposed per batch-of-2048 rows:
//       Ct[(row/2048)*N + col][row%2048]  (used to produce V^T)
// CTA 128x128, BK=16, 8 warps (2x4), warp tile 64x32, mma m16n8k8 tf32,
// double-buffered smem, ldmatrix fragment loads.
// Requires M,N % 128 == 0, K % 16 == 0.
// ---------------------------------------------------------------------------
#define BM 128
#define BN 128
#define BK 16
#define ASTR 20   // padded k-stride (words); conflict-free for ldmatrix + mostly for STS

__device__ __forceinline__ uint32_t f2tf32(float f) {
    uint32_t u;
    asm("cvt.rna.tf32.f32 %0, %1;" : "=r"(u) : "f"(f));
    return u;
}

__device__ __forceinline__ void mma_tf32(float* c, const uint32_t* a, const uint32_t* b) {
    asm volatile(
        "mma.sync.aligned.m16n8k8.row.col.f32.tf32.tf32.f32 "
        "{%0,%1,%2,%3}, {%4,%5,%6,%7}, {%8,%9}, {%0,%1,%2,%3};"
        : "+f"(c[0]), "+f"(c[1]), "+f"(c[2]), "+f"(c[3])
        : "r"(a[0]), "r"(a[1]), "r"(a[2]), "r"(a[3]),
          "r"(b[0]), "r"(b[1]));
}

__device__ __forceinline__ void ldsm4(uint32_t* r, uint32_t saddr) {
    asm volatile("ldmatrix.sync.aligned.m8n8.x4.shared.b16 {%0,%1,%2,%3}, [%4];"
                 : "=r"(r[0]), "=r"(r[1]), "=r"(r[2]), "=r"(r[3])
                 : "r"(saddr));
}

template <bool TSTORE>
__global__ __launch_bounds__(256, 2)
void gemm_nt(const float* __restrict__ A, const float* __restrict__ Bm,
             const float* __restrict__ bias, float* __restrict__ C,
             int M, int N, int K, float scale,
             long long sA, long long sB, long long sC)
{
    __shared__ uint32_t As[2][BM * ASTR];
    __shared__ uint32_t Bs[2][BM * ASTR];

    const int tid = threadIdx.x;
    const int bz  = blockIdx.z;
    A  += (size_t)bz * sA;
    Bm += (size_t)bz * sB;
    C  += (size_t)bz * sC;

    const int bm0 = blockIdx.y * BM;
    const int bn0 = blockIdx.x * BN;

    // ---- gmem loaders: 128 rows x 16 k = 512 float4; 2 per thread ----
    const int lr = tid >> 2;            // 0..63 (+64 for second)
    const int lc = (tid & 3) << 2;      // 0,4,8,12
    const float* aptr = A  + (size_t)(bm0 + lr) * K + lc;
    const float* bptr = Bm + (size_t)(bn0 + lr) * K + lc;
    const size_t rstep = (size_t)64 * K;

    float4 ra[2], rb[2];

    // ---- warp/fragment mapping ----
    const int wid  = tid >> 5;
    const int lane = tid & 31;
    const int g = lane >> 2;
    const int t = lane & 3;
    const int wm = (wid >> 2) * 64;     // 0 / 64
    const int wn = (wid & 3) * 32;      // 0/32/64/96

    // ldmatrix per-lane address components
    const int bsel = lane >> 3;         // block 0..3
    const int rr   = lane & 7;
    const int a_row = ((bsel & 1) << 3) + rr;   // +0/+8 row within 16
    const int a_kc  = (bsel >> 1) << 2;         // +0/+4 k
    const int b_row = ((bsel >> 1) << 3) + rr;  // +0/+8 row within 16
    const int b_kc  = (bsel & 1) << 2;          // +0/+4 k

    const uint32_t as_base = (uint32_t)__cvta_generic_to_shared(&As[0][0]);
    const uint32_t bs_base = (uint32_t)__cvta_generic_to_shared(&Bs[0][0]);
    // lane-resolved fragment base addresses (buf 0, mi/pr = 0, ks = 0)
    const uint32_t a_lane = as_base + (((wm + a_row) * ASTR + a_kc) << 2);
    const uint32_t b_lane = bs_base + (((wn + b_row) * ASTR + b_kc) << 2);
    const uint32_t bufstep = BM * ASTR * 4;

    float acc[4][4][4];
#pragma unroll
    for (int mi = 0; mi < 4; mi++)
#pragma unroll
        for (int ni = 0; ni < 4; ni++)
#pragma unroll
            for (int r = 0; r < 4; r++) acc[mi][ni][r] = 0.0f;

    // ---- prologue: load + store tile 0 ----
    ra[0] = *(const float4*)(aptr);
    ra[1] = *(const float4*)(aptr + rstep);
    rb[0] = *(const float4*)(bptr);
    rb[1] = *(const float4*)(bptr + rstep);
    aptr += BK; bptr += BK;
    {
        uint32_t* pa0 = &As[0][lr * ASTR + lc];
        uint32_t* pa1 = &As[0][(lr + 64) * ASTR + lc];
        pa0[0]=f2tf32(ra[0].x); pa0[1]=f2tf32(ra[0].y); pa0[2]=f2tf32(ra[0].z); pa0[3]=f2tf32(ra[0].w);
        pa1[0]=f2tf32(ra[1].x); pa1[1]=f2tf32(ra[1].y); pa1[2]=f2tf32(ra[1].z); pa1[3]=f2tf32(ra[1].w);
        uint32_t* pb0 = &Bs[0][lr * ASTR + lc];
        uint32_t* pb1 = &Bs[0][(lr + 64) * ASTR + lc];
        pb0[0]=f2tf32(rb[0].x); pb0[1]=f2tf32(rb[0].y); pb0[2]=f2tf32(rb[0].z); pb0[3]=f2tf32(rb[0].w);
        pb1[0]=f2tf32(rb[1].x); pb1[1]=f2tf32(rb[1].y); pb1[2]=f2tf32(rb[1].z); pb1[3]=f2tf32(rb[1].w);
    }
    __syncthreads();

    int buf = 0;
    for (int kt = 0; kt < K; kt += BK) {
        const bool more = (kt + BK < K);
        if (more) {
            ra[0] = *(const float4*)(aptr);
            ra[1] = *(const float4*)(aptr + rstep);
            rb[0] = *(const float4*)(bptr);
            rb[1] = *(const float4*)(bptr + rstep);
            aptr += BK; bptr += BK;
        }

        // ---- compute current buffer ----
        const uint32_t abase = a_lane + buf * bufstep;
        const uint32_t bbase = b_lane + buf * bufstep;
#pragma unroll
        for (int ks = 0; ks < 2; ks++) {
            const uint32_t ko = ks * 32;        // 8 words * 4B
            uint32_t af[4][4];
#pragma unroll
            for (int mi = 0; mi < 4; mi++)
                ldsm4(af[mi], abase + mi * (16 * ASTR * 4) + ko);
            uint32_t bf[2][4];
#pragma unroll
            for (int pr = 0; pr < 2; pr++)
                ldsm4(bf[pr], bbase + pr * (16 * ASTR * 4) + ko);
#pragma unroll
            for (int mi = 0; mi < 4; mi++)
#pragma unroll
                for (int ni = 0; ni < 4; ni++)
                    mma_tf32(acc[mi][ni], af[mi], &bf[ni >> 1][(ni & 1) * 2]);
        }

        // ---- stage next tile into the other buffer ----
        if (more) {
            const int nb = buf ^ 1;
            uint32_t* pa0 = &As[nb][lr * ASTR + lc];
            uint32_t* pa1 = &As[nb][(lr + 64) * ASTR + lc];
            pa0[0]=f2tf32(ra[0].x); pa0[1]=f2tf32(ra[0].y); pa0[2]=f2tf32(ra[0].z); pa0[3]=f2tf32(ra[0].w);
            pa1[0]=f2tf32(ra[1].x); pa1[1]=f2tf32(ra[1].y); pa1[2]=f2tf32(ra[1].z); pa1[3]=f2tf32(ra[1].w);
            uint32_t* pb0 = &Bs[nb][lr * ASTR + lc];
            uint32_t* pb1 = &Bs[nb][(lr + 64) * ASTR + lc];
            pb0[0]=f2tf32(rb[0].x); pb0[1]=f2tf32(rb[0].y); pb0[2]=f2tf32(rb[0].z); pb0[3]=f2tf32(rb[0].w);
            pb1[0]=f2tf32(rb[1].x); pb1[1]=f2tf32(rb[1].y); pb1[2]=f2tf32(rb[1].z); pb1[3]=f2tf32(rb[1].w);
            __syncthreads();
            buf = nb;
        }
    }

    // ---- epilogue ----
    float bfr[4][2];
#pragma unroll
    for (int ni = 0; ni < 4; ni++) {
        const int col = bn0 + wn + ni * 8 + t * 2;
        bfr[ni][0] = bias ? bias[col] : 0.0f;
        bfr[ni][1] = bias ? bias[col + 1] : 0.0f;
    }

    if (TSTORE) {
        // Ct[(row/2048)*N + col][row%2048]
#pragma unroll
        for (int mi = 0; mi < 4; mi++) {
            const int row0 = bm0 + wm + mi * 16 + g;
            const int bb = row0 >> 11;
            const int m0 = row0 & 2047;
#pragma unroll
            for (int ni = 0; ni < 4; ni++) {
                const int col = bn0 + wn + ni * 8 + t * 2;
                float* c0 = C + ((size_t)bb * N + col) * NSEQ;
                float* c1 = C + ((size_t)bb * N + col + 1) * NSEQ;
                c0[m0]     = acc[mi][ni][0] * scale + bfr[ni][0];
                c1[m0]     = acc[mi][ni][1] * scale + bfr[ni][1];
                c0[m0 + 8] = acc[mi][ni][2] * scale + bfr[ni][0];
                c1[m0 + 8] = acc[mi][ni][3] * scale + bfr[ni][1];
            }
        }
    } else {
#pragma unroll
        for (int mi = 0; mi < 4; mi++) {
            const int row0 = bm0 + wm + mi * 16 + g;
#pragma unroll
            for (int ni = 0; ni < 4; ni++) {
                const int col = bn0 + wn + ni * 8 + t * 2;
                float2 v0, v1;
                v0.x = acc[mi][ni][0] * scale + bfr[ni][0];
                v0.y = acc[mi][ni][1] * scale + bfr[ni][1];
                v1.x = acc[mi][ni][2] * scale + bfr[ni][0];
                v1.y = acc[mi][ni][3] * scale + bfr[ni][1];
                *(float2*)(C + (size_t)row0 * N + col)       = v0;
                *(float2*)(C + (size_t)(row0 + 8) * N + col) = v1;
            }
        }
    }
}

// ---------------------------------------------------------------------------
// Register-resident row softmax: N=2048, one block of 256 per row, in place.
// One gmem read + one gmem write per element.
// ---------------------------------------------------------------------------
__global__ __launch_bounds__(256)
void softmax_kernel(float* __restrict__ S)
{
    float4* row = (float4*)(S + (size_t)blockIdx.x * NSEQ);
    const int tid  = threadIdx.x;
    const int lane = tid & 31;
    const int wid  = tid >> 5;
    __shared__ float red[8];

    float4 v0 = row[tid];
    float4 v1 = row[tid + 256];

    float m = fmaxf(fmaxf(fmaxf(v0.x, v0.y), fmaxf(v0.z, v0.w)),
                    fmaxf(fmaxf(v1.x, v1.y), fmaxf(v1.z, v1.w)));
#pragma unroll
    for (int o = 16; o > 0; o >>= 1) m = fmaxf(m, __shfl_xor_sync(0xffffffffu, m, o));
    if (lane == 0) red[wid] = m;
    __syncthreads();
    m = red[0];
#pragma unroll
    for (int i = 1; i < 8; i++) m = fmaxf(m, red[i]);

    v0.x = __expf(v0.x - m); v0.y = __expf(v0.y - m);
    v0.z = __expf(v0.z - m); v0.w = __expf(v0.w - m);
    v1.x = __expf(v1.x - m); v1.y = __expf(v1.y - m);
    v1.z = __expf(v1.z - m); v1.w = __expf(v1.w - m);

    float s = v0.x + v0.y + v0.z + v0.w + v1.x + v1.y + v1.z + v1.w;
#pragma unroll
    for (int o = 16; o > 0; o >>= 1) s += __shfl_xor_sync(0xffffffffu, s, o);
    __syncthreads();               // red reuse safety
    if (lane == 0) red[wid] = s;
    __syncthreads();
    float tot = red[0];
#pragma unroll
    for (int i = 1; i < 8; i++) tot += red[i];
    const float inv = 1.0f / tot;

    v0.x *= inv; v0.y *= inv; v0.z *= inv; v0.w *= inv;
    v1.x *= inv; v1.y *= inv; v1.z *= inv; v1.w *= inv;
    row[tid]       = v0;
    row[tid + 256] = v1;
}

// ---------------------------------------------------------------------------
// Launch
// ---------------------------------------------------------------------------
extern "C" void kernel_launch(void* const* d_in, const int* in_sizes, int n_in,
                              void* d_out, int out_size)
{
    const float* x  = (const float*)d_in[0];
    const float* Wq = (const float*)d_in[1];
    const float* bq = (const float*)d_in[2];
    const float* Wk = (const float*)d_in[3];
    const float* bk = (const float*)d_in[4];
    const float* Wv = (const float*)d_in[5];
    const float* bv = (const float*)d_in[6];
    float* out = (float*)d_out;

    float *q, *k, *vt, *s;
    cudaGetSymbolAddress((void**)&q,  g_q);
    cudaGetSymbolAddress((void**)&k,  g_k);
    cudaGetSymbolAddress((void**)&vt, g_vt);
    cudaGetSymbolAddress((void**)&s,  g_s);

    const float attn_scale = 1.0f / sqrtf((float)DIM);   // 1/32

    dim3 block(256);

    // 1) QKV projections (NT). V writes its output transposed per batch.
    {
        dim3 grid(DIM / BN, MX / BM, 1);
        gemm_nt<false><<<grid, block>>>(x, Wq, bq, q,  MX, DIM, DIM, 1.0f, 0, 0, 0);
        gemm_nt<false><<<grid, block>>>(x, Wk, bk, k,  MX, DIM, DIM, 1.0f, 0, 0, 0);
        gemm_nt<true ><<<grid, block>>>(x, Wv, bv, vt, MX, DIM, DIM, 1.0f, 0, 0, 0);
    }

    // 2) S = scale * Q @ K^T   (per-batch NT)
    {
        dim3 grid(NSEQ / BN, NSEQ / BM, B_SZ);
        gemm_nt<false><<<grid, block>>>(q, k, nullptr, s,
                                        NSEQ, NSEQ, DIM, attn_scale,
                                        (long long)NSEQ * DIM,
                                        (long long)NSEQ * DIM,
                                        (long long)NSEQ * NSEQ);
    }

    // 3) softmax rows
    softmax_kernel<<<B_SZ * NSEQ, 256>>>(s);

    // 4) out = P @ Vt^T  (per-batch NT: out[n][d] = sum_m P[n][m] * Vt[d][m])
    {
        dim3 grid(DIM / BN, NSEQ / BM, B_SZ);
        gemm_nt<false><<<grid, block>>>(s, vt, nullptr, out,
                                        NSEQ, DIM, NSEQ, 1.0f,
                                        (long long)NSEQ * NSEQ,
                                        (long long)DIM * NSEQ,
                                        (long long)NSEQ * DIM);
    }
}